// round 3
// baseline (speedup 1.0000x reference)
#include <cuda_runtime.h>

// CrossCompressUnit: B=262144 rows, D=64.
// v_out = v * (e·w_vv) + e * (v·w_ev) + bias_v
// e_out = v * (e·w_ve) + e * (v·w_ee) + bias_e
//
// R2: 8 lanes per row (was 16). Each lane handles 2 float4 chunks (elements
// [4l..4l+3] and [4l+32..4l+35]). Halves shuffle traffic per row (96 vs 256
// SHFLs) and doubles front-batched LDG.128 per thread (MLP_p1=4).

#define D 64
#define LANES_PER_ROW 8   // each lane covers 2 float4 = 8 floats

__global__ __launch_bounds__(256)
void cross_compress_kernel(const float* __restrict__ v,
                           const float* __restrict__ e,
                           const float* __restrict__ w_vv,
                           const float* __restrict__ w_ev,
                           const float* __restrict__ w_ve,
                           const float* __restrict__ w_ee,
                           const float* __restrict__ bias_v,
                           const float* __restrict__ bias_e,
                           float* __restrict__ v_out,
                           float* __restrict__ e_out,
                           int n_rows)
{
    const int tid = blockIdx.x * blockDim.x + threadIdx.x;
    const int row = tid >> 3;                 // tid / 8
    const int l   = tid & 7;                  // lane within row group
    if (row >= n_rows) return;

    const long long b0 = (long long)row * 16 + l;      // first float4 chunk
    const long long b1 = b0 + 8;                       // second float4 chunk

    const float4* v4p = (const float4*)v;
    const float4* e4p = (const float4*)e;

    // Front-batch the 4 streaming loads (MLP_p1 = 4)
    float4 va = __ldg(&v4p[b0]);
    float4 vb = __ldg(&v4p[b1]);
    float4 ea = __ldg(&e4p[b0]);
    float4 eb = __ldg(&e4p[b1]);

    // weight slices for this lane's two chunks (L1-resident after wave 1)
    const float4* wvv4 = (const float4*)w_vv;
    const float4* wev4 = (const float4*)w_ev;
    const float4* wve4 = (const float4*)w_ve;
    const float4* wee4 = (const float4*)w_ee;

    float4 wvv_a = __ldg(&wvv4[l]), wvv_b = __ldg(&wvv4[l + 8]);
    float4 wev_a = __ldg(&wev4[l]), wev_b = __ldg(&wev4[l + 8]);
    float4 wve_a = __ldg(&wve4[l]), wve_b = __ldg(&wve4[l + 8]);
    float4 wee_a = __ldg(&wee4[l]), wee_b = __ldg(&wee4[l + 8]);

    // 4 partial dot products over this lane's 8 elements
    float a, b, c, d;
    a = ea.x*wvv_a.x + ea.y*wvv_a.y + ea.z*wvv_a.z + ea.w*wvv_a.w
      + eb.x*wvv_b.x + eb.y*wvv_b.y + eb.z*wvv_b.z + eb.w*wvv_b.w;   // e·w_vv
    b = va.x*wev_a.x + va.y*wev_a.y + va.z*wev_a.z + va.w*wev_a.w
      + vb.x*wev_b.x + vb.y*wev_b.y + vb.z*wev_b.z + vb.w*wev_b.w;   // v·w_ev
    c = ea.x*wve_a.x + ea.y*wve_a.y + ea.z*wve_a.z + ea.w*wve_a.w
      + eb.x*wve_b.x + eb.y*wve_b.y + eb.z*wve_b.z + eb.w*wve_b.w;   // e·w_ve
    d = va.x*wee_a.x + va.y*wee_a.y + va.z*wee_a.z + va.w*wee_a.w
      + vb.x*wee_b.x + vb.y*wee_b.y + vb.z*wee_b.z + vb.w*wee_b.w;   // v·w_ee

    // reduce across the 8-lane group (masks 4,2,1 stay in-group)
    #pragma unroll
    for (int m = 4; m >= 1; m >>= 1) {
        a += __shfl_xor_sync(0xffffffffu, a, m);
        b += __shfl_xor_sync(0xffffffffu, b, m);
        c += __shfl_xor_sync(0xffffffffu, c, m);
        d += __shfl_xor_sync(0xffffffffu, d, m);
    }

    float4 bva = __ldg(&((const float4*)bias_v)[l]);
    float4 bvb = __ldg(&((const float4*)bias_v)[l + 8]);
    float4 bea = __ldg(&((const float4*)bias_e)[l]);
    float4 beb = __ldg(&((const float4*)bias_e)[l + 8]);

    float4 o;
    // v_out chunk a
    o.x = fmaf(va.x, a, fmaf(ea.x, b, bva.x));
    o.y = fmaf(va.y, a, fmaf(ea.y, b, bva.y));
    o.z = fmaf(va.z, a, fmaf(ea.z, b, bva.z));
    o.w = fmaf(va.w, a, fmaf(ea.w, b, bva.w));
    ((float4*)v_out)[b0] = o;
    // v_out chunk b
    o.x = fmaf(vb.x, a, fmaf(eb.x, b, bvb.x));
    o.y = fmaf(vb.y, a, fmaf(eb.y, b, bvb.y));
    o.z = fmaf(vb.z, a, fmaf(eb.z, b, bvb.z));
    o.w = fmaf(vb.w, a, fmaf(eb.w, b, bvb.w));
    ((float4*)v_out)[b1] = o;
    // e_out chunk a
    o.x = fmaf(va.x, c, fmaf(ea.x, d, bea.x));
    o.y = fmaf(va.y, c, fmaf(ea.y, d, bea.y));
    o.z = fmaf(va.z, c, fmaf(ea.z, d, bea.z));
    o.w = fmaf(va.w, c, fmaf(ea.w, d, bea.w));
    ((float4*)e_out)[b0] = o;
    // e_out chunk b
    o.x = fmaf(vb.x, c, fmaf(eb.x, d, beb.x));
    o.y = fmaf(vb.y, c, fmaf(eb.y, d, beb.y));
    o.z = fmaf(vb.z, c, fmaf(eb.z, d, beb.z));
    o.w = fmaf(vb.w, c, fmaf(eb.w, d, beb.w));
    ((float4*)e_out)[b1] = o;
}

extern "C" void kernel_launch(void* const* d_in, const int* in_sizes, int n_in,
                              void* d_out, int out_size)
{
    const float* v      = (const float*)d_in[0];
    const float* e      = (const float*)d_in[1];
    const float* w_vv   = (const float*)d_in[2];
    const float* w_ev   = (const float*)d_in[3];
    const float* w_ve   = (const float*)d_in[4];
    const float* w_ee   = (const float*)d_in[5];
    const float* bias_v = (const float*)d_in[6];
    const float* bias_e = (const float*)d_in[7];

    const int n_rows = in_sizes[0] / D;           // B = 262144

    float* out   = (float*)d_out;
    float* v_out = out;                            // [B, D]
    float* e_out = out + (long long)n_rows * D;    // [B, D]

    const int threads = 256;
    const long long total_threads = (long long)n_rows * LANES_PER_ROW;
    const int blocks = (int)((total_threads + threads - 1) / threads);

    cross_compress_kernel<<<blocks, threads>>>(v, e, w_vv, w_ev, w_ve, w_ee,
                                               bias_v, bias_e, v_out, e_out,
                                               n_rows);
}

// round 5
// speedup vs baseline: 1.0107x; 1.0107x over previous
#include <cuda_runtime.h>

// CrossCompressUnit: B=262144 rows, D=64.
// v_out = v * (e·w_vv) + e * (v·w_ev) + bias_v
// e_out = v * (e·w_ve) + e * (v·w_ee) + bias_e
//
// R3: R2 shape (8 lanes/row, 2 float4 chunks per lane, 4 front-batched
// LDG.128) + streaming cache policy: __ldcs on v/e (touched once, evict
// first), __stcs on outputs (drain dirty lines in bursts). Weights/biases
// stay __ldg (hot, reused by every wave).

#define D 64
#define LANES_PER_ROW 8   // each lane covers 2 float4 = 8 floats

__global__ __launch_bounds__(256)
void cross_compress_kernel(const float* __restrict__ v,
                           const float* __restrict__ e,
                           const float* __restrict__ w_vv,
                           const float* __restrict__ w_ev,
                           const float* __restrict__ w_ve,
                           const float* __restrict__ w_ee,
                           const float* __restrict__ bias_v,
                           const float* __restrict__ bias_e,
                           float* __restrict__ v_out,
                           float* __restrict__ e_out,
                           int n_rows)
{
    const int tid = blockIdx.x * blockDim.x + threadIdx.x;
    const int row = tid >> 3;                 // tid / 8
    const int l   = tid & 7;                  // lane within row group
    if (row >= n_rows) return;

    const long long b0 = (long long)row * 16 + l;      // first float4 chunk
    const long long b1 = b0 + 8;                       // second float4 chunk

    const float4* v4p = (const float4*)v;
    const float4* e4p = (const float4*)e;

    // Front-batch the 4 streaming loads (MLP_p1 = 4), evict-first policy
    float4 va = __ldcs(&v4p[b0]);
    float4 vb = __ldcs(&v4p[b1]);
    float4 ea = __ldcs(&e4p[b0]);
    float4 eb = __ldcs(&e4p[b1]);

    // weight slices for this lane's two chunks (L1/L2-resident, cached)
    const float4* wvv4 = (const float4*)w_vv;
    const float4* wev4 = (const float4*)w_ev;
    const float4* wve4 = (const float4*)w_ve;
    const float4* wee4 = (const float4*)w_ee;

    float4 wvv_a = __ldg(&wvv4[l]), wvv_b = __ldg(&wvv4[l + 8]);
    float4 wev_a = __ldg(&wev4[l]), wev_b = __ldg(&wev4[l + 8]);
    float4 wve_a = __ldg(&wve4[l]), wve_b = __ldg(&wve4[l + 8]);
    float4 wee_a = __ldg(&wee4[l]), wee_b = __ldg(&wee4[l + 8]);

    // 4 partial dot products over this lane's 8 elements
    float a, b, c, d;
    a = ea.x*wvv_a.x + ea.y*wvv_a.y + ea.z*wvv_a.z + ea.w*wvv_a.w
      + eb.x*wvv_b.x + eb.y*wvv_b.y + eb.z*wvv_b.z + eb.w*wvv_b.w;   // e·w_vv
    b = va.x*wev_a.x + va.y*wev_a.y + va.z*wev_a.z + va.w*wev_a.w
      + vb.x*wev_b.x + vb.y*wev_b.y + vb.z*wev_b.z + vb.w*wev_b.w;   // v·w_ev
    c = ea.x*wve_a.x + ea.y*wve_a.y + ea.z*wve_a.z + ea.w*wve_a.w
      + eb.x*wve_b.x + eb.y*wve_b.y + eb.z*wve_b.z + eb.w*wve_b.w;   // e·w_ve
    d = va.x*wee_a.x + va.y*wee_a.y + va.z*wee_a.z + va.w*wee_a.w
      + vb.x*wee_b.x + vb.y*wee_b.y + vb.z*wee_b.z + vb.w*wee_b.w;   // v·w_ee

    // reduce across the 8-lane group (masks 4,2,1 stay in-group)
    #pragma unroll
    for (int m = 4; m >= 1; m >>= 1) {
        a += __shfl_xor_sync(0xffffffffu, a, m);
        b += __shfl_xor_sync(0xffffffffu, b, m);
        c += __shfl_xor_sync(0xffffffffu, c, m);
        d += __shfl_xor_sync(0xffffffffu, d, m);
    }

    float4 bva = __ldg(&((const float4*)bias_v)[l]);
    float4 bvb = __ldg(&((const float4*)bias_v)[l + 8]);
    float4 bea = __ldg(&((const float4*)bias_e)[l]);
    float4 beb = __ldg(&((const float4*)bias_e)[l + 8]);

    float4 o;
    // v_out chunk a
    o.x = fmaf(va.x, a, fmaf(ea.x, b, bva.x));
    o.y = fmaf(va.y, a, fmaf(ea.y, b, bva.y));
    o.z = fmaf(va.z, a, fmaf(ea.z, b, bva.z));
    o.w = fmaf(va.w, a, fmaf(ea.w, b, bva.w));
    __stcs(&((float4*)v_out)[b0], o);
    // v_out chunk b
    o.x = fmaf(vb.x, a, fmaf(eb.x, b, bvb.x));
    o.y = fmaf(vb.y, a, fmaf(eb.y, b, bvb.y));
    o.z = fmaf(vb.z, a, fmaf(eb.z, b, bvb.z));
    o.w = fmaf(vb.w, a, fmaf(eb.w, b, bvb.w));
    __stcs(&((float4*)v_out)[b1], o);
    // e_out chunk a
    o.x = fmaf(va.x, c, fmaf(ea.x, d, bea.x));
    o.y = fmaf(va.y, c, fmaf(ea.y, d, bea.y));
    o.z = fmaf(va.z, c, fmaf(ea.z, d, bea.z));
    o.w = fmaf(va.w, c, fmaf(ea.w, d, bea.w));
    __stcs(&((float4*)e_out)[b0], o);
    // e_out chunk b
    o.x = fmaf(vb.x, c, fmaf(eb.x, d, beb.x));
    o.y = fmaf(vb.y, c, fmaf(eb.y, d, beb.y));
    o.z = fmaf(vb.z, c, fmaf(eb.z, d, beb.z));
    o.w = fmaf(vb.w, c, fmaf(eb.w, d, beb.w));
    __stcs(&((float4*)e_out)[b1], o);
}

extern "C" void kernel_launch(void* const* d_in, const int* in_sizes, int n_in,
                              void* d_out, int out_size)
{
    const float* v      = (const float*)d_in[0];
    const float* e      = (const float*)d_in[1];
    const float* w_vv   = (const float*)d_in[2];
    const float* w_ev   = (const float*)d_in[3];
    const float* w_ve   = (const float*)d_in[4];
    const float* w_ee   = (const float*)d_in[5];
    const float* bias_v = (const float*)d_in[6];
    const float* bias_e = (const float*)d_in[7];

    const int n_rows = in_sizes[0] / D;           // B = 262144

    float* out   = (float*)d_out;
    float* v_out = out;                            // [B, D]
    float* e_out = out + (long long)n_rows * D;    // [B, D]

    const int threads = 256;
    const long long total_threads = (long long)n_rows * LANES_PER_ROW;
    const int blocks = (int)((total_threads + threads - 1) / threads);

    cross_compress_kernel<<<blocks, threads>>>(v, e, w_vv, w_ev, w_ve, w_ee,
                                               bias_v, bias_e, v_out, e_out,
                                               n_rows);
}